// round 5
// baseline (speedup 1.0000x reference)
#include <cuda_runtime.h>

#define BB   2
#define CC   128
#define HCH  64
#define TT   5
#define TC   4
#define HH   48
#define WIW  48
#define HW   2304
#define NKEY 196
#define NGRP 25

// Scratch (device globals; no allocations allowed)
__device__ float theta_s[BB * HW * HCH];          // [b][p][h], pre-scaled by 8
__device__ float phi_s[BB * TC * HW * HCH];       // [b][t][p][h]
__device__ float g_s[BB * TC * HW * HCH];         // [b][t][p][h]
__device__ float y_s[BB * HW * HCH];              // [b][p][hc]

// ---------------------------------------------------------------------------
// Kernel 1: projections theta (t==0), phi+g (t>=1)
// grid (36, B, T), 256 threads, dyn smem = xs[128*64] + wsm[128*132]
// ---------------------------------------------------------------------------
__global__ __launch_bounds__(256) void proj_kernel(
    const float* __restrict__ x,
    const float* __restrict__ w_theta,
    const float* __restrict__ w_phi,
    const float* __restrict__ w_g) {
  extern __shared__ float sm[];
  float* xs  = sm;                 // [c][px]  128 x 64
  float* wsm = sm + 128 * 64;      // [c][n]   128 x 132 (padded)

  const int tile = blockIdx.x, b = blockIdx.y, t = blockIdx.z;
  const int tid = threadIdx.x;
  const int p0 = tile * 64;

  for (int i = tid; i < 128 * 64; i += 256) {
    int c = i >> 6, px = i & 63;
    xs[i] = x[((b * CC + c) * TT + t) * HW + p0 + px];
  }
  if (t == 0) {
    for (int i = tid; i < 64 * 128; i += 256) {
      int n = i >> 7, c = i & 127;
      wsm[c * 132 + n] = w_theta[i];
    }
  } else {
    for (int i = tid; i < 128 * 128; i += 256) {
      int n = i >> 7, c = i & 127;
      wsm[c * 132 + n] = (n < 64) ? w_phi[n * 128 + c] : w_g[(n - 64) * 128 + c];
    }
  }
  __syncthreads();

  const int px4 = (tid & 15) * 4;

  if (t == 0) {
    const int n0 = (tid >> 4) * 4;
    float acc[4][4];
#pragma unroll
    for (int i = 0; i < 4; i++)
#pragma unroll
      for (int j = 0; j < 4; j++) acc[i][j] = 0.f;

    for (int c = 0; c < 128; c++) {
      float4 xv = *(const float4*)(xs + c * 64 + px4);
      float4 wv = *(const float4*)(wsm + c * 132 + n0);
      float xa[4] = {xv.x, xv.y, xv.z, xv.w};
      float wa[4] = {wv.x, wv.y, wv.z, wv.w};
#pragma unroll
      for (int i = 0; i < 4; i++)
#pragma unroll
        for (int j = 0; j < 4; j++) acc[i][j] = fmaf(xa[i], wa[j], acc[i][j]);
    }
#pragma unroll
    for (int i = 0; i < 4; i++) {
      int pix = p0 + px4 + i;
      float4 o = make_float4(8.f * acc[i][0], 8.f * acc[i][1],
                             8.f * acc[i][2], 8.f * acc[i][3]);
      *(float4*)(theta_s + (size_t)(b * HW + pix) * 64 + n0) = o;
    }
  } else {
    const int n0 = (tid >> 4) * 8;
    float acc[4][8];
#pragma unroll
    for (int i = 0; i < 4; i++)
#pragma unroll
      for (int j = 0; j < 8; j++) acc[i][j] = 0.f;

    for (int c = 0; c < 128; c++) {
      float4 xv = *(const float4*)(xs + c * 64 + px4);
      float4 w0 = *(const float4*)(wsm + c * 132 + n0);
      float4 w1 = *(const float4*)(wsm + c * 132 + n0 + 4);
      float xa[4] = {xv.x, xv.y, xv.z, xv.w};
      float wa[8] = {w0.x, w0.y, w0.z, w0.w, w1.x, w1.y, w1.z, w1.w};
#pragma unroll
      for (int i = 0; i < 4; i++)
#pragma unroll
        for (int j = 0; j < 8; j++) acc[i][j] = fmaf(xa[i], wa[j], acc[i][j]);
    }
    float* dst = (n0 < 64) ? phi_s : g_s;
    const int nn = n0 & 63;
#pragma unroll
    for (int i = 0; i < 4; i++) {
      int pix = p0 + px4 + i;
      float* d = dst + ((size_t)((b * TC + (t - 1)) * HW + pix)) * 64 + nn;
      *(float4*)(d)     = make_float4(acc[i][0], acc[i][1], acc[i][2], acc[i][3]);
      *(float4*)(d + 4) = make_float4(acc[i][4], acc[i][5], acc[i][6], acc[i][7]);
    }
  }
}

// ---------------------------------------------------------------------------
// Kernel 2: attention with the reference's RAW-RESHAPE g_p semantics.
//   logits: att_e[k] via clean q.phi  (k = t*49 + dy*7 + dx)
//   value : y[hc] = sum_k att[k] * G[64k+hc],
//           G[h*196 + t*49 + r] = g[h, t, nbr(r)]
//   i.e. contribution of (h, rem): att[3h + ((4h+rem)>>6)] * g[h,rem]
//        accumulated into y[(4h + rem) & 63].
// 1 warp = 1 pixel (8 pixels/block). Lane handles h = lane and h = lane+32
// (same rotation class since 4*(h+32) == 4h mod 64).
// ---------------------------------------------------------------------------
__device__ __forceinline__ float dot4(float4 a, float4 b) {
  return fmaf(a.x, b.x, fmaf(a.y, b.y, fmaf(a.z, b.z, a.w * b.w)));
}

__global__ __launch_bounds__(256) void attn_kernel() {
  __shared__ float logits[8][200];
  __shared__ int   ofs[8][196];
  __shared__ float ysm[8][64];
  const int wid = threadIdx.x >> 5, lane = threadIdx.x & 31;
  const int pid = blockIdx.x * 8 + wid;
  const int b = pid / HW, p = pid % HW;
  const int py = p / WIW, px = p % WIW;
  const int cp = lane & 3, kg = lane >> 2;

  // Precompute per-key g/phi offsets (element offset of channel 0)
#pragma unroll
  for (int j = 0; j < 7; j++) {
    int rem = lane + j * 32;
    if (rem < NKEY) {
      int t = rem / 49, r = rem % 49;
      int dy = r / 7, dx = r % 7;
      int yy = min(max(py + dy - 3, 0), HH - 1);
      int xx = min(max(px + dx - 3, 0), WIW - 1);
      ofs[wid][rem] = ((b * TC + t) * HW + yy * WIW + xx) * 64;
    }
  }
  __syncwarp();

  // ---- Pass 1: logits (clean) ----
  const float4* th4 = (const float4*)theta_s + (size_t)(b * HW + p) * 16 + cp * 4;
  const float4 q0 = th4[0], q1 = th4[1], q2 = th4[2], q3 = th4[3];

#pragma unroll
  for (int grp = 0; grp < NGRP; grp++) {
    int k = grp * 8 + kg;
    int kc = min(k, NKEY - 1);
    const float4* ph = (const float4*)(phi_s + ofs[wid][kc]) + cp * 4;
    float s = dot4(q0, ph[0]) + dot4(q1, ph[1]) + dot4(q2, ph[2]) + dot4(q3, ph[3]);
    s += __shfl_xor_sync(0xffffffffu, s, 1);
    s += __shfl_xor_sync(0xffffffffu, s, 2);
    if (cp == 0 && k < NKEY) logits[wid][k] = s;
  }
  __syncwarp();

  // ---- Softmax over 196 (store unnormalized e, fold 1/sum at the end) ----
  float lv[7], m = -1e30f;
#pragma unroll
  for (int j = 0; j < 7; j++) {
    int idx = lane + j * 32;
    lv[j] = (idx < NKEY) ? logits[wid][idx] : -1e30f;
    m = fmaxf(m, lv[j]);
  }
#pragma unroll
  for (int off = 16; off >= 1; off >>= 1)
    m = fmaxf(m, __shfl_xor_sync(0xffffffffu, m, off));
  float ssum = 0.f;
#pragma unroll
  for (int j = 0; j < 7; j++) {
    int idx = lane + j * 32;
    if (idx < NKEY) {
      float e = __expf(lv[j] - m);
      logits[wid][idx] = e;
      ssum += e;
    }
  }
#pragma unroll
  for (int off = 16; off >= 1; off >>= 1)
    ssum += __shfl_xor_sync(0xffffffffu, ssum, off);
  const float rinv = 1.f / ssum;
  __syncwarp();

  // ---- Pass 2: scrambled AV ----
  float acc[64];
#pragma unroll
  for (int s = 0; s < 64; s++) acc[s] = 0.f;

#pragma unroll
  for (int rem = 0; rem < NKEY; rem++) {
    int o = ofs[wid][rem];
    float g1 = g_s[o + lane];         // channel h = lane
    float g2 = g_s[o + lane + 32];    // channel h = lane + 32
    int wi = 3 * lane + ((4 * lane + rem) >> 6);   // k for h = lane
    float w1 = logits[wid][wi];
    float w2 = logits[wid][wi + 98];               // k for h = lane+32
    acc[rem & 63] = fmaf(w1, g1, fmaf(w2, g2, acc[rem & 63]));
  }

  // Merge rotation classes: lanes l and l+16 share class (4h mod 64 equal)
#pragma unroll
  for (int s = 0; s < 64; s++)
    acc[s] += __shfl_xor_sync(0xffffffffu, acc[s], 16);

  ysm[wid][lane] = 0.f;
  ysm[wid][lane + 32] = 0.f;
  __syncwarp();
  if (lane < 16) {
#pragma unroll
    for (int s = 0; s < 64; s++) {
      int hc = (4 * lane + s) & 63;
      ysm[wid][hc] += acc[s];
    }
  }
  __syncwarp();

  float* yp = y_s + (size_t)(b * HW + p) * 64;
  yp[lane]      = ysm[wid][lane] * rinv;
  yp[lane + 32] = ysm[wid][lane + 32] * rinv;
}

// ---------------------------------------------------------------------------
// Kernel 3 (raw-reshape of Y[B,HW,64] to [B,64,1,48,48]):
// with pix = u*64+v:  out[b][c][pix] = x[b][c][0][pix]
//                     + sum_h w_out[c][h] * Y[b][h*36 + u][v]
// ---------------------------------------------------------------------------
__global__ __launch_bounds__(256) void outproj_kernel(
    const float* __restrict__ x,
    const float* __restrict__ w_out,
    float* __restrict__ out) {
  extern __shared__ float sm[];
  float* wsm = sm;                 // [c][h] 128 x 64
  float* ys  = sm + 128 * 64;      // [h][v] 64 x 65 (padded)

  const int u = blockIdx.x, b = blockIdx.y;
  const int tid = threadIdx.x;
  const int p0 = u * 64;

  for (int i = tid; i < 128 * 64; i += 256) wsm[i] = w_out[i];
  for (int i = tid; i < 64 * 64; i += 256) {
    int hh = i >> 6, v = i & 63;
    ys[hh * 65 + v] = y_s[(size_t)(b * HW + hh * 36 + u) * 64 + v];
  }
  __syncthreads();

  const int v4 = (tid & 15) * 4;
  const int c0 = (tid >> 4) * 8;
  float acc[4][8];
#pragma unroll
  for (int i = 0; i < 4; i++)
#pragma unroll
    for (int j = 0; j < 8; j++) acc[i][j] = 0.f;

  for (int h4 = 0; h4 < 64; h4 += 4) {
    float4 wv[8];
#pragma unroll
    for (int j = 0; j < 8; j++)
      wv[j] = *(const float4*)(wsm + (c0 + j) * 64 + h4);
    float yv[4][4];
#pragma unroll
    for (int q = 0; q < 4; q++)
#pragma unroll
      for (int i = 0; i < 4; i++)
        yv[i][q] = ys[(h4 + q) * 65 + v4 + i];
#pragma unroll
    for (int i = 0; i < 4; i++)
#pragma unroll
      for (int j = 0; j < 8; j++) {
        float wa[4] = {wv[j].x, wv[j].y, wv[j].z, wv[j].w};
#pragma unroll
        for (int q = 0; q < 4; q++)
          acc[i][j] = fmaf(yv[i][q], wa[q], acc[i][j]);
      }
  }

#pragma unroll
  for (int i = 0; i < 4; i++) {
    int pix = p0 + v4 + i;
#pragma unroll
    for (int j = 0; j < 8; j++) {
      int c = c0 + j;
      float xi = x[((size_t)(b * CC + c) * TT) * HW + pix];
      out[(size_t)(b * CC + c) * HW + pix] = xi + acc[i][j];
    }
  }
}

// ---------------------------------------------------------------------------
extern "C" void kernel_launch(void* const* d_in, const int* in_sizes, int n_in,
                              void* d_out, int out_size) {
  const float* x       = (const float*)d_in[0];
  const float* w_theta = (const float*)d_in[1];
  const float* w_phi   = (const float*)d_in[2];
  const float* w_g     = (const float*)d_in[3];
  const float* w_out   = (const float*)d_in[4];
  float* out = (float*)d_out;

  const int sm1 = (128 * 64 + 128 * 132) * 4;   // 100352 B
  const int sm3 = (128 * 64 + 64 * 65) * 4;     // 49408 B
  cudaFuncSetAttribute(proj_kernel, cudaFuncAttributeMaxDynamicSharedMemorySize, sm1);
  cudaFuncSetAttribute(outproj_kernel, cudaFuncAttributeMaxDynamicSharedMemorySize, sm3);

  proj_kernel<<<dim3(36, BB, TT), 256, sm1>>>(x, w_theta, w_phi, w_g);
  attn_kernel<<<576, 256>>>();
  outproj_kernel<<<dim3(36, BB), 256, sm3>>>(x, w_out, out);
}

// round 6
// speedup vs baseline: 1.6223x; 1.6223x over previous
#include <cuda_runtime.h>
#include <cuda_bf16.h>

#define BB   2
#define CC   128
#define HCH  64
#define TT   5
#define TC   4
#define HH   48
#define WIW  48
#define HW   2304
#define NKEY 196
#define NGRP 25

// Scratch (device globals; no allocations allowed)
__device__ float theta_s[BB * HW * HCH];                         // [b][p][h] fp32, pre-scaled by 8
__device__ __align__(16) __nv_bfloat16 phi_b[BB * TC * HW * HCH]; // [pix][h] bf16
__device__ __align__(16) __nv_bfloat16 g_b[BB * TC * HW * HCH];   // [pix][h] bf16
__device__ float y_s[BB * HW * HCH];                             // [b][p][hc]

// packed f32x2 helpers (sm_103a)
#define FMA_F32X2(d, a, b) \
  asm("fma.rn.f32x2 %0, %1, %2, %0;" : "+l"(d) : "l"(a), "l"(b))
#define PACK_F32X2(out, lo, hi) \
  asm("mov.b64 %0, {%1, %2};" : "=l"(out) : "r"(__float_as_uint(lo)), "r"(__float_as_uint(hi)))
#define UNPACK_F32X2(lo, hi, in) \
  do { unsigned _l, _h; asm("mov.b64 {%0, %1}, %2;" : "=r"(_l), "=r"(_h) : "l"(in)); \
       lo = __uint_as_float(_l); hi = __uint_as_float(_h); } while (0)

__device__ __forceinline__ unsigned pack_bf2(float a, float b) {
  __nv_bfloat162 h = __floats2bfloat162_rn(a, b);
  return *(unsigned*)&h;
}

// ---------------------------------------------------------------------------
// Kernel 1: projections. t==0 -> theta (64n, fp32 out), t>=1 -> phi|g (128n, bf16 out)
// grid (18, B, 5), 256 threads. Tile 128px x {64|128}n, 8px x {4|8}n per thread.
// dyn smem = xs[128c][128px] + wsm[128c][132n] = 130KB
// ---------------------------------------------------------------------------
__global__ __launch_bounds__(256) void proj_kernel(
    const float* __restrict__ x,
    const float* __restrict__ w_theta,
    const float* __restrict__ w_phi,
    const float* __restrict__ w_g) {
  extern __shared__ float sm[];
  float* xs  = sm;                  // [c][px] 128 x 128
  float* wsm = sm + 128 * 128;      // [c][n]  128 x 132 (padded)

  const int tile = blockIdx.x, b = blockIdx.y, t = blockIdx.z;
  const int tid = threadIdx.x;
  const int p0 = tile * 128;

  for (int i = tid; i < 128 * 128; i += 256) {
    int c = i >> 7, px = i & 127;
    xs[i] = x[((b * CC + c) * TT + t) * HW + p0 + px];
  }
  if (t == 0) {
    for (int i = tid; i < 64 * 128; i += 256) {
      int n = i >> 7, c = i & 127;
      wsm[c * 132 + n] = w_theta[i];
    }
  } else {
    for (int i = tid; i < 128 * 128; i += 256) {
      int n = i >> 7, c = i & 127;
      wsm[c * 132 + n] = (n < 64) ? w_phi[n * 128 + c] : w_g[(n - 64) * 128 + c];
    }
  }
  __syncthreads();

  const int px8 = (tid & 15) * 8;

  if (t == 0) {
    const int n0 = (tid >> 4) * 4;
    unsigned long long acc[4][4];
#pragma unroll
    for (int i = 0; i < 4; i++)
#pragma unroll
      for (int j = 0; j < 4; j++) acc[i][j] = 0ull;

#pragma unroll 2
    for (int c = 0; c < 128; c++) {
      const ulonglong2* xp = (const ulonglong2*)(xs + c * 128 + px8);
      ulonglong2 xa = xp[0], xb = xp[1];
      unsigned long long xr[4] = {xa.x, xa.y, xb.x, xb.y};
      float4 wv = *(const float4*)(wsm + c * 132 + n0);
      float wf[4] = {wv.x, wv.y, wv.z, wv.w};
      unsigned long long wd[4];
#pragma unroll
      for (int j = 0; j < 4; j++) PACK_F32X2(wd[j], wf[j], wf[j]);
#pragma unroll
      for (int i = 0; i < 4; i++)
#pragma unroll
        for (int j = 0; j < 4; j++) FMA_F32X2(acc[i][j], xr[i], wd[j]);
    }
#pragma unroll
    for (int i = 0; i < 4; i++) {
      float flo[4], fhi[4];
#pragma unroll
      for (int j = 0; j < 4; j++) UNPACK_F32X2(flo[j], fhi[j], acc[i][j]);
      int pixlo = p0 + px8 + 2 * i;
      float* d0 = theta_s + (size_t)(b * HW + pixlo) * 64 + n0;
      *(float4*)(d0)      = make_float4(8.f*flo[0], 8.f*flo[1], 8.f*flo[2], 8.f*flo[3]);
      *(float4*)(d0 + 64) = make_float4(8.f*fhi[0], 8.f*fhi[1], 8.f*fhi[2], 8.f*fhi[3]);
    }
  } else {
    const int n0 = (tid >> 4) * 8;
    unsigned long long acc[4][8];
#pragma unroll
    for (int i = 0; i < 4; i++)
#pragma unroll
      for (int j = 0; j < 8; j++) acc[i][j] = 0ull;

#pragma unroll 2
    for (int c = 0; c < 128; c++) {
      const ulonglong2* xp = (const ulonglong2*)(xs + c * 128 + px8);
      ulonglong2 xa = xp[0], xb = xp[1];
      unsigned long long xr[4] = {xa.x, xa.y, xb.x, xb.y};
      float4 w0 = *(const float4*)(wsm + c * 132 + n0);
      float4 w1 = *(const float4*)(wsm + c * 132 + n0 + 4);
      float wf[8] = {w0.x, w0.y, w0.z, w0.w, w1.x, w1.y, w1.z, w1.w};
      unsigned long long wd[8];
#pragma unroll
      for (int j = 0; j < 8; j++) PACK_F32X2(wd[j], wf[j], wf[j]);
#pragma unroll
      for (int i = 0; i < 4; i++)
#pragma unroll
        for (int j = 0; j < 8; j++) FMA_F32X2(acc[i][j], xr[i], wd[j]);
    }

    __nv_bfloat16* base = (n0 < 64) ? phi_b : g_b;
    const int ch = n0 & 63;
    const size_t rowb = (size_t)((b * TC + (t - 1)) * HW);
#pragma unroll
    for (int i = 0; i < 4; i++) {
      float flo[8], fhi[8];
#pragma unroll
      for (int j = 0; j < 8; j++) UNPACK_F32X2(flo[j], fhi[j], acc[i][j]);
      int pixlo = p0 + px8 + 2 * i;
      uint4 slo, shi;
      slo.x = pack_bf2(flo[0], flo[1]); slo.y = pack_bf2(flo[2], flo[3]);
      slo.z = pack_bf2(flo[4], flo[5]); slo.w = pack_bf2(flo[6], flo[7]);
      shi.x = pack_bf2(fhi[0], fhi[1]); shi.y = pack_bf2(fhi[2], fhi[3]);
      shi.z = pack_bf2(fhi[4], fhi[5]); shi.w = pack_bf2(fhi[6], fhi[7]);
      *(uint4*)(base + (rowb + pixlo) * 64 + ch)     = slo;
      *(uint4*)(base + (rowb + pixlo + 1) * 64 + ch) = shi;
    }
  }
}

// ---------------------------------------------------------------------------
// Kernel 2: attention (raw-reshape g_p semantics), phi/g in bf16.
// 1 warp = 1 pixel, 8 pixels/block, grid 576.
// ---------------------------------------------------------------------------
__global__ __launch_bounds__(256) void attn_kernel() {
  __shared__ float logits[8][200];
  __shared__ int   ofs[8][196];
  __shared__ float ysm[8][64];
  const int wid = threadIdx.x >> 5, lane = threadIdx.x & 31;
  const int pid = blockIdx.x * 8 + wid;
  const int b = pid / HW, p = pid % HW;
  const int py = p / WIW, px = p % WIW;
  const int cp = lane & 3, kg = lane >> 2;

#pragma unroll
  for (int j = 0; j < 7; j++) {
    int rem = lane + j * 32;
    if (rem < NKEY) {
      int t = rem / 49, r = rem % 49;
      int dy = r / 7, dx = r % 7;
      int yy = min(max(py + dy - 3, 0), HH - 1);
      int xx = min(max(px + dx - 3, 0), WIW - 1);
      ofs[wid][rem] = ((b * TC + t) * HW + yy * WIW + xx) * 64;
    }
  }
  __syncwarp();

  // ---- Pass 1: logits ----
  const float* qp = theta_s + (size_t)(b * HW + p) * 64 + cp * 16;
  float q[16];
#pragma unroll
  for (int j = 0; j < 4; j++) {
    float4 qv = *(const float4*)(qp + j * 4);
    q[j*4+0] = qv.x; q[j*4+1] = qv.y; q[j*4+2] = qv.z; q[j*4+3] = qv.w;
  }

#pragma unroll
  for (int grp = 0; grp < NGRP; grp++) {
    int k = grp * 8 + kg;
    int kc = min(k, NKEY - 1);
    const uint4* ph = (const uint4*)(phi_b + ofs[wid][kc]) + cp * 2;
    uint4 A = ph[0], B2 = ph[1];
    unsigned r[8] = {A.x, A.y, A.z, A.w, B2.x, B2.y, B2.z, B2.w};
    float s = 0.f;
#pragma unroll
    for (int w = 0; w < 8; w++) {
      float lo = __uint_as_float(r[w] << 16);
      float hi = __uint_as_float(r[w] & 0xffff0000u);
      s = fmaf(q[2*w], lo, fmaf(q[2*w+1], hi, s));
    }
    s += __shfl_xor_sync(0xffffffffu, s, 1);
    s += __shfl_xor_sync(0xffffffffu, s, 2);
    if (cp == 0 && k < NKEY) logits[wid][k] = s;
  }
  __syncwarp();

  // ---- Softmax over 196 (unnormalized e; 1/sum folded at end) ----
  float lv[7], m = -1e30f;
#pragma unroll
  for (int j = 0; j < 7; j++) {
    int idx = lane + j * 32;
    lv[j] = (idx < NKEY) ? logits[wid][idx] : -1e30f;
    m = fmaxf(m, lv[j]);
  }
#pragma unroll
  for (int off = 16; off >= 1; off >>= 1)
    m = fmaxf(m, __shfl_xor_sync(0xffffffffu, m, off));
  float ssum = 0.f;
#pragma unroll
  for (int j = 0; j < 7; j++) {
    int idx = lane + j * 32;
    if (idx < NKEY) {
      float e = __expf(lv[j] - m);
      logits[wid][idx] = e;
      ssum += e;
    }
  }
#pragma unroll
  for (int off = 16; off >= 1; off >>= 1)
    ssum += __shfl_xor_sync(0xffffffffu, ssum, off);
  const float rinv = 1.f / ssum;
  __syncwarp();

  // ---- Pass 2: scrambled AV ----
  float acc[64];
#pragma unroll
  for (int s = 0; s < 64; s++) acc[s] = 0.f;

#pragma unroll
  for (int rem = 0; rem < NKEY; rem++) {
    int o = ofs[wid][rem];
    float g1 = __bfloat162float(g_b[o + lane]);
    float g2 = __bfloat162float(g_b[o + lane + 32]);
    int wi = 3 * lane + ((4 * lane + rem) >> 6);
    float w1 = logits[wid][wi];
    float w2 = logits[wid][wi + 98];
    acc[rem & 63] = fmaf(w1, g1, fmaf(w2, g2, acc[rem & 63]));
  }

#pragma unroll
  for (int s = 0; s < 64; s++)
    acc[s] += __shfl_xor_sync(0xffffffffu, acc[s], 16);

  ysm[wid][lane] = 0.f;
  ysm[wid][lane + 32] = 0.f;
  __syncwarp();
  if (lane < 16) {
#pragma unroll
    for (int s = 0; s < 64; s++) {
      int hc = (4 * lane + s) & 63;
      ysm[wid][hc] += acc[s];
    }
  }
  __syncwarp();

  float* yp = y_s + (size_t)(b * HW + p) * 64;
  yp[lane]      = ysm[wid][lane] * rinv;
  yp[lane + 32] = ysm[wid][lane + 32] * rinv;
}

// ---------------------------------------------------------------------------
// Kernel 3 (raw-reshape of Y[B,HW,64] to [B,64,1,48,48]):
// with pix = u*64+v:  out[b][c][pix] = x[b][c][0][pix]
//                     + sum_h w_out[c][h] * Y[b][h*36 + u][v]
// ---------------------------------------------------------------------------
__global__ __launch_bounds__(256) void outproj_kernel(
    const float* __restrict__ x,
    const float* __restrict__ w_out,
    float* __restrict__ out) {
  extern __shared__ float sm[];
  float* wsm = sm;                 // [c][h] 128 x 64
  float* ys  = sm + 128 * 64;      // [h][v] 64 x 65 (padded)

  const int u = blockIdx.x, b = blockIdx.y;
  const int tid = threadIdx.x;
  const int p0 = u * 64;

  for (int i = tid; i < 128 * 64; i += 256) wsm[i] = w_out[i];
  for (int i = tid; i < 64 * 64; i += 256) {
    int hh = i >> 6, v = i & 63;
    ys[hh * 65 + v] = y_s[(size_t)(b * HW + hh * 36 + u) * 64 + v];
  }
  __syncthreads();

  const int v4 = (tid & 15) * 4;
  const int c0 = (tid >> 4) * 8;
  float acc[4][8];
#pragma unroll
  for (int i = 0; i < 4; i++)
#pragma unroll
    for (int j = 0; j < 8; j++) acc[i][j] = 0.f;

  for (int h4 = 0; h4 < 64; h4 += 4) {
    float4 wv[8];
#pragma unroll
    for (int j = 0; j < 8; j++)
      wv[j] = *(const float4*)(wsm + (c0 + j) * 64 + h4);
    float yv[4][4];
#pragma unroll
    for (int q = 0; q < 4; q++)
#pragma unroll
      for (int i = 0; i < 4; i++)
        yv[i][q] = ys[(h4 + q) * 65 + v4 + i];
#pragma unroll
    for (int i = 0; i < 4; i++)
#pragma unroll
      for (int j = 0; j < 8; j++) {
        float wa[4] = {wv[j].x, wv[j].y, wv[j].z, wv[j].w};
#pragma unroll
        for (int q = 0; q < 4; q++)
          acc[i][j] = fmaf(yv[i][q], wa[q], acc[i][j]);
      }
  }

#pragma unroll
  for (int i = 0; i < 4; i++) {
    int pix = p0 + v4 + i;
#pragma unroll
    for (int j = 0; j < 8; j++) {
      int c = c0 + j;
      float xi = x[((size_t)(b * CC + c) * TT) * HW + pix];
      out[(size_t)(b * CC + c) * HW + pix] = xi + acc[i][j];
    }
  }
}

// ---------------------------------------------------------------------------
extern "C" void kernel_launch(void* const* d_in, const int* in_sizes, int n_in,
                              void* d_out, int out_size) {
  const float* x       = (const float*)d_in[0];
  const float* w_theta = (const float*)d_in[1];
  const float* w_phi   = (const float*)d_in[2];
  const float* w_g     = (const float*)d_in[3];
  const float* w_out   = (const float*)d_in[4];
  float* out = (float*)d_out;

  const int sm1 = (128 * 128 + 128 * 132) * 4;  // 133120 B
  const int sm3 = (128 * 64 + 64 * 65) * 4;     // 49408 B
  cudaFuncSetAttribute(proj_kernel, cudaFuncAttributeMaxDynamicSharedMemorySize, sm1);
  cudaFuncSetAttribute(outproj_kernel, cudaFuncAttributeMaxDynamicSharedMemorySize, sm3);

  proj_kernel<<<dim3(18, BB, TT), 256, sm1>>>(x, w_theta, w_phi, w_g);
  attn_kernel<<<576, 256>>>();
  outproj_kernel<<<dim3(36, BB), 256, sm3>>>(x, w_out, out);
}

// round 9
// speedup vs baseline: 1.8473x; 1.1387x over previous
#include <cuda_runtime.h>
#include <cuda_bf16.h>

#define BB   2
#define CC   128
#define HCH  64
#define TT   5
#define TC   4
#define HH   48
#define WIW  48
#define HW   2304
#define NKEY 196
#define NGRP 25

// Scratch (device globals; no allocations allowed)
__device__ float theta_s[BB * HW * HCH];                          // [b][p][h] fp32, pre-scaled by 8
__device__ __align__(16) __nv_bfloat16 phi_b[BB * TC * HW * HCH]; // [pix][h] bf16
__device__ __align__(16) __nv_bfloat16 g_b[BB * TC * HW * HCH];   // [pix][h] bf16
__device__ float y_s[BB * HW * HCH];                              // [b][p][hc]

// packed f32x2 helpers (sm_103a)
#define FMA_F32X2(d, a, b) \
  asm("fma.rn.f32x2 %0, %1, %2, %0;" : "+l"(d) : "l"(a), "l"(b))
#define PACK_F32X2(out, lo, hi) \
  asm("mov.b64 %0, {%1, %2};" : "=l"(out) : "r"(__float_as_uint(lo)), "r"(__float_as_uint(hi)))
#define UNPACK_F32X2(lo, hi, in) \
  do { unsigned _l, _h; asm("mov.b64 {%0, %1}, %2;" : "=r"(_l), "=r"(_h) : "l"(in)); \
       lo = __uint_as_float(_l); hi = __uint_as_float(_h); } while (0)

__device__ __forceinline__ unsigned pack_bf2(float a, float b) {
  __nv_bfloat162 h = __floats2bfloat162_rn(a, b);
  return *(unsigned*)&h;
}

// ---------------------------------------------------------------------------
// Kernel 1: projections. Tile 64px x {64|128}n, 256 threads, grid (36,B,5).
// f32x2 packed along n: weight pairs load free as 64-bit from smem.
// dyn smem = xs[128c][64px] + wsm[128c][132n] = 99.5KB -> 2 CTA/SM.
// ---------------------------------------------------------------------------
__global__ __launch_bounds__(256) void proj_kernel(
    const float* __restrict__ x,
    const float* __restrict__ w_theta,
    const float* __restrict__ w_phi,
    const float* __restrict__ w_g) {
  extern __shared__ float sm[];
  float* xs  = sm;                 // [c][px] 128 x 64
  float* wsm = sm + 128 * 64;      // [c][n]  128 x 132 (padded)

  const int tile = blockIdx.x, b = blockIdx.y, t = blockIdx.z;
  const int tid = threadIdx.x;
  const int p0 = tile * 64;

  for (int i = tid; i < 128 * 64; i += 256) {
    int c = i >> 6, px = i & 63;
    xs[i] = x[((b * CC + c) * TT + t) * HW + p0 + px];
  }
  if (t == 0) {
    for (int i = tid; i < 64 * 128; i += 256) {
      int n = i >> 7, c = i & 127;
      wsm[c * 132 + n] = w_theta[i];
    }
  } else {
    for (int i = tid; i < 128 * 128; i += 256) {
      int n = i >> 7, c = i & 127;
      wsm[c * 132 + n] = (n < 64) ? w_phi[n * 128 + c] : w_g[(n - 64) * 128 + c];
    }
  }
  __syncthreads();

  const int px4 = (tid & 15) * 4;

  if (t == 0) {
    // 4px x 4n per thread; acc lanes = (n0+2j, n0+2j+1)
    const int n0 = (tid >> 4) * 4;
    unsigned long long acc[4][2];
#pragma unroll
    for (int i = 0; i < 4; i++) { acc[i][0] = 0ull; acc[i][1] = 0ull; }

#pragma unroll 4
    for (int c = 0; c < 128; c++) {
      float4 xv = *(const float4*)(xs + c * 64 + px4);
      ulonglong2 wp = *(const ulonglong2*)(wsm + c * 132 + n0);  // 2 n-pairs
      float xa[4] = {xv.x, xv.y, xv.z, xv.w};
      unsigned long long xd[4];
#pragma unroll
      for (int i = 0; i < 4; i++) PACK_F32X2(xd[i], xa[i], xa[i]);
#pragma unroll
      for (int i = 0; i < 4; i++) {
        FMA_F32X2(acc[i][0], xd[i], wp.x);
        FMA_F32X2(acc[i][1], xd[i], wp.y);
      }
    }
#pragma unroll
    for (int i = 0; i < 4; i++) {
      float f0, f1, f2, f3;
      UNPACK_F32X2(f0, f1, acc[i][0]);
      UNPACK_F32X2(f2, f3, acc[i][1]);
      int pix = p0 + px4 + i;
      *(float4*)(theta_s + (size_t)(b * HW + pix) * 64 + n0) =
          make_float4(8.f * f0, 8.f * f1, 8.f * f2, 8.f * f3);
    }
  } else {
    // 4px x 8n per thread; 4 n-pairs load free as ulonglong2 x2
    const int n0 = (tid >> 4) * 8;
    unsigned long long acc[4][4];
#pragma unroll
    for (int i = 0; i < 4; i++)
#pragma unroll
      for (int j = 0; j < 4; j++) acc[i][j] = 0ull;

#pragma unroll 4
    for (int c = 0; c < 128; c++) {
      float4 xv = *(const float4*)(xs + c * 64 + px4);
      ulonglong2 wa = *(const ulonglong2*)(wsm + c * 132 + n0);
      ulonglong2 wb = *(const ulonglong2*)(wsm + c * 132 + n0 + 4);
      unsigned long long wp[4] = {wa.x, wa.y, wb.x, wb.y};
      float xa[4] = {xv.x, xv.y, xv.z, xv.w};
      unsigned long long xd[4];
#pragma unroll
      for (int i = 0; i < 4; i++) PACK_F32X2(xd[i], xa[i], xa[i]);
#pragma unroll
      for (int i = 0; i < 4; i++)
#pragma unroll
        for (int j = 0; j < 4; j++) FMA_F32X2(acc[i][j], xd[i], wp[j]);
    }

    __nv_bfloat16* base = (n0 < 64) ? phi_b : g_b;
    const int ch = n0 & 63;
    const size_t rowb = (size_t)((b * TC + (t - 1)) * HW);
#pragma unroll
    for (int i = 0; i < 4; i++) {
      float f[8];
#pragma unroll
      for (int j = 0; j < 4; j++) UNPACK_F32X2(f[2 * j], f[2 * j + 1], acc[i][j]);
      int pix = p0 + px4 + i;
      uint4 s;
      s.x = pack_bf2(f[0], f[1]); s.y = pack_bf2(f[2], f[3]);
      s.z = pack_bf2(f[4], f[5]); s.w = pack_bf2(f[6], f[7]);
      *(uint4*)(base + (rowb + pix) * 64 + ch) = s;
    }
  }
}

// ---------------------------------------------------------------------------
// Kernel 2: attention (raw-reshape g_p semantics), phi/g in bf16.
// 1 warp = 1 pixel, 8 pixels/block, grid 576.
// ---------------------------------------------------------------------------
__global__ __launch_bounds__(256) void attn_kernel() {
  __shared__ float logits[8][200];
  __shared__ int   ofs[8][196];
  __shared__ float ysm[8][64];
  const int wid = threadIdx.x >> 5, lane = threadIdx.x & 31;
  const int pid = blockIdx.x * 8 + wid;
  const int b = pid / HW, p = pid % HW;
  const int py = p / WIW, px = p % WIW;
  const int cp = lane & 3, kg = lane >> 2;

#pragma unroll
  for (int j = 0; j < 7; j++) {
    int rem = lane + j * 32;
    if (rem < NKEY) {
      int t = rem / 49, r = rem % 49;
      int dy = r / 7, dx = r % 7;
      int yy = min(max(py + dy - 3, 0), HH - 1);
      int xx = min(max(px + dx - 3, 0), WIW - 1);
      ofs[wid][rem] = ((b * TC + t) * HW + yy * WIW + xx) * 64;
    }
  }
  __syncwarp();

  // ---- Pass 1: logits ----
  const float* qp = theta_s + (size_t)(b * HW + p) * 64 + cp * 16;
  float q[16];
#pragma unroll
  for (int j = 0; j < 4; j++) {
    float4 qv = *(const float4*)(qp + j * 4);
    q[j*4+0] = qv.x; q[j*4+1] = qv.y; q[j*4+2] = qv.z; q[j*4+3] = qv.w;
  }

#pragma unroll
  for (int grp = 0; grp < NGRP; grp++) {
    int k = grp * 8 + kg;
    int kc = min(k, NKEY - 1);
    const uint4* ph = (const uint4*)(phi_b + ofs[wid][kc]) + cp * 2;
    uint4 A = ph[0], B2 = ph[1];
    unsigned r[8] = {A.x, A.y, A.z, A.w, B2.x, B2.y, B2.z, B2.w};
    float s = 0.f;
#pragma unroll
    for (int w = 0; w < 8; w++) {
      float lo = __uint_as_float(r[w] << 16);
      float hi = __uint_as_float(r[w] & 0xffff0000u);
      s = fmaf(q[2*w], lo, fmaf(q[2*w+1], hi, s));
    }
    s += __shfl_xor_sync(0xffffffffu, s, 1);
    s += __shfl_xor_sync(0xffffffffu, s, 2);
    if (cp == 0 && k < NKEY) logits[wid][k] = s;
  }
  __syncwarp();

  // ---- Softmax over 196 (unnormalized e; 1/sum folded at end) ----
  float lv[7], m = -1e30f;
#pragma unroll
  for (int j = 0; j < 7; j++) {
    int idx = lane + j * 32;
    lv[j] = (idx < NKEY) ? logits[wid][idx] : -1e30f;
    m = fmaxf(m, lv[j]);
  }
#pragma unroll
  for (int off = 16; off >= 1; off >>= 1)
    m = fmaxf(m, __shfl_xor_sync(0xffffffffu, m, off));
  float ssum = 0.f;
#pragma unroll
  for (int j = 0; j < 7; j++) {
    int idx = lane + j * 32;
    if (idx < NKEY) {
      float e = __expf(lv[j] - m);
      logits[wid][idx] = e;
      ssum += e;
    }
  }
#pragma unroll
  for (int off = 16; off >= 1; off >>= 1)
    ssum += __shfl_xor_sync(0xffffffffu, ssum, off);
  const float rinv = 1.f / ssum;
  __syncwarp();

  // ---- Pass 2: scrambled AV, chunked for MLP, fully unrolled ----
  float acc[64];
#pragma unroll
  for (int s = 0; s < 64; s++) acc[s] = 0.f;

#pragma unroll
  for (int base = 0; base < 196; base += 4) {
    int oo[4];
    float g1[4], g2[4], w1[4], w2[4];
#pragma unroll
    for (int j = 0; j < 4; j++) oo[j] = ofs[wid][base + j];
#pragma unroll
    for (int j = 0; j < 4; j++) {
      g1[j] = __bfloat162float(g_b[oo[j] + lane]);
      g2[j] = __bfloat162float(g_b[oo[j] + lane + 32]);
    }
#pragma unroll
    for (int j = 0; j < 4; j++) {
      int wi = 3 * lane + ((4 * lane + base + j) >> 6);
      w1[j] = logits[wid][wi];
      w2[j] = logits[wid][wi + 98];
    }
#pragma unroll
    for (int j = 0; j < 4; j++) {
      int s = (base + j) & 63;
      acc[s] = fmaf(w1[j], g1[j], fmaf(w2[j], g2[j], acc[s]));
    }
  }

#pragma unroll
  for (int s = 0; s < 64; s++)
    acc[s] += __shfl_xor_sync(0xffffffffu, acc[s], 16);

  ysm[wid][lane] = 0.f;
  ysm[wid][lane + 32] = 0.f;
  __syncwarp();
  if (lane < 16) {
#pragma unroll
    for (int s = 0; s < 64; s++) {
      int hc = (4 * lane + s) & 63;
      ysm[wid][hc] += acc[s];
    }
  }
  __syncwarp();

  float* yp = y_s + (size_t)(b * HW + p) * 64;
  yp[lane]      = ysm[wid][lane] * rinv;
  yp[lane + 32] = ysm[wid][lane + 32] * rinv;
}

// ---------------------------------------------------------------------------
// Kernel 3 (raw-reshape of Y[B,HW,64] to [B,64,1,48,48]):
// with pix = u*64+v:  out[b][c][pix] = x[b][c][0][pix]
//                     + sum_h w_out[c][h] * Y[b][h*36 + u][v]
// ---------------------------------------------------------------------------
__global__ __launch_bounds__(256) void outproj_kernel(
    const float* __restrict__ x,
    const float* __restrict__ w_out,
    float* __restrict__ out) {
  extern __shared__ float sm[];
  float* wsm = sm;                 // [c][h] 128 x 64
  float* ys  = sm + 128 * 64;      // [h][v] 64 x 65 (padded)

  const int u = blockIdx.x, b = blockIdx.y;
  const int tid = threadIdx.x;
  const int p0 = u * 64;

  for (int i = tid; i < 128 * 64; i += 256) wsm[i] = w_out[i];
  for (int i = tid; i < 64 * 64; i += 256) {
    int hh = i >> 6, v = i & 63;
    ys[hh * 65 + v] = y_s[(size_t)(b * HW + hh * 36 + u) * 64 + v];
  }
  __syncthreads();

  const int v4 = (tid & 15) * 4;
  const int c0 = (tid >> 4) * 8;
  float acc[4][8];
#pragma unroll
  for (int i = 0; i < 4; i++)
#pragma unroll
    for (int j = 0; j < 8; j++) acc[i][j] = 0.f;

  for (int h4 = 0; h4 < 64; h4 += 4) {
    float4 wv[8];
#pragma unroll
    for (int j = 0; j < 8; j++)
      wv[j] = *(const float4*)(wsm + (c0 + j) * 64 + h4);
    float yv[4][4];
#pragma unroll
    for (int q = 0; q < 4; q++)
#pragma unroll
      for (int i = 0; i < 4; i++)
        yv[i][q] = ys[(h4 + q) * 65 + v4 + i];
#pragma unroll
    for (int i = 0; i < 4; i++)
#pragma unroll
      for (int j = 0; j < 8; j++) {
        float wa[4] = {wv[j].x, wv[j].y, wv[j].z, wv[j].w};
#pragma unroll
        for (int q = 0; q < 4; q++)
          acc[i][j] = fmaf(yv[i][q], wa[q], acc[i][j]);
      }
  }

#pragma unroll
  for (int i = 0; i < 4; i++) {
    int pix = p0 + v4 + i;
#pragma unroll
    for (int j = 0; j < 8; j++) {
      int c = c0 + j;
      float xi = x[((size_t)(b * CC + c) * TT) * HW + pix];
      out[(size_t)(b * CC + c) * HW + pix] = xi + acc[i][j];
    }
  }
}

// ---------------------------------------------------------------------------
extern "C" void kernel_launch(void* const* d_in, const int* in_sizes, int n_in,
                              void* d_out, int out_size) {
  const float* x       = (const float*)d_in[0];
  const float* w_theta = (const float*)d_in[1];
  const float* w_phi   = (const float*)d_in[2];
  const float* w_g     = (const float*)d_in[3];
  const float* w_out   = (const float*)d_in[4];
  float* out = (float*)d_out;

  const int sm1 = (128 * 64 + 128 * 132) * 4;   // 99.5 KB -> 2 CTA/SM
  const int sm3 = (128 * 64 + 64 * 65) * 4;     // 49408 B
  cudaFuncSetAttribute(proj_kernel, cudaFuncAttributeMaxDynamicSharedMemorySize, sm1);
  cudaFuncSetAttribute(outproj_kernel, cudaFuncAttributeMaxDynamicSharedMemorySize, sm3);

  proj_kernel<<<dim3(36, BB, TT), 256, sm1>>>(x, w_theta, w_phi, w_g);
  attn_kernel<<<576, 256>>>();
  outproj_kernel<<<dim3(36, BB), 256, sm3>>>(x, w_out, out);
}